// round 12
// baseline (speedup 1.0000x reference)
#include <cuda_runtime.h>
#include <cuda_fp16.h>
#include <cuda_bf16.h>
#include <cstdint>

#define N_NODESC 100000
#define NFEAT    512
#define HID      64
#define NCLS     40
#define N_EDGESC 3200000
#define KPROP    10
#define H2ROW    20            // 20 half2 = 80B of data per node row
#define SROWB    96            // padded row stride in bytes (32B-aligned -> 3 sectors)
#define H2STRIDE (SROWB / 4)   // 24 half2 per padded row

#define SCAN_B 512
#define NSB ((N_NODESC + SCAN_B - 1) / SCAN_B)   // 196

typedef unsigned long long ull;

// ---- static scratch (no allocations allowed) ----
__device__ int     g_is64;
__device__ int     g_indeg[N_NODESC];
__device__ float   g_dinv[N_NODESC];
__device__ int     g_offs[N_NODESC + 1];
__device__ int     g_cursor[N_NODESC];
__device__ int     g_bsum[NSB];
__device__ int     g_src[N_EDGESC];
__device__ float   g_h1[(size_t)N_NODESC * HID];
__device__ __half2 g_hist[(size_t)(KPROP + 1) * N_NODESC * H2STRIDE];   // s_0..s_10

// ---------------- dtype detection: int64 edge_index has zero high words ----
__global__ void k_detect(const int* __restrict__ ei) {
    int nz = 0;
    for (int t = threadIdx.x; t < 64; t += 32)
        nz |= (ei[2 * t + 1] != 0);
    unsigned b = __ballot_sync(0xffffffffu, nz);
    if (threadIdx.x == 0) g_is64 = (b == 0u);
}

__device__ __forceinline__ int load_src(const int* ei, int e, int is64) {
    return is64 ? ei[2 * e] : ei[e];
}
__device__ __forceinline__ int load_dst(const int* ei, int e, int is64) {
    return is64 ? ei[2 * (N_EDGESC + e)] : ei[N_EDGESC + e];
}

// ---------------- preprocessing ----------------
__global__ void k_zero() {
    int i = blockIdx.x * blockDim.x + threadIdx.x;
    if (i < N_NODESC) g_indeg[i] = 0;
}

__global__ void k_count(const int* __restrict__ ei) {
    int e = blockIdx.x * blockDim.x + threadIdx.x;
    if (e < N_EDGESC) {
        int dst = load_dst(ei, e, g_is64);
        if ((unsigned)dst < N_NODESC) atomicAdd(&g_indeg[dst], 1);
    }
}

__global__ void k_scan1() {
    __shared__ int s[SCAN_B];
    int i = blockIdx.x * SCAN_B + threadIdx.x;
    int v = (i < N_NODESC) ? g_indeg[i] : 0;
    s[threadIdx.x] = v;
    __syncthreads();
    #pragma unroll
    for (int off = 1; off < SCAN_B; off <<= 1) {
        int t = (threadIdx.x >= off) ? s[threadIdx.x - off] : 0;
        __syncthreads();
        s[threadIdx.x] += t;
        __syncthreads();
    }
    if (i < N_NODESC) g_offs[i] = s[threadIdx.x] - v;
    if (threadIdx.x == SCAN_B - 1) g_bsum[blockIdx.x] = s[SCAN_B - 1];
}

__global__ void k_scan2p() {
    __shared__ int s[256];
    int i = threadIdx.x;
    int v = (i < NSB) ? g_bsum[i] : 0;
    s[i] = v;
    __syncthreads();
    #pragma unroll
    for (int off = 1; off < 256; off <<= 1) {
        int t = (i >= off) ? s[i - off] : 0;
        __syncthreads();
        s[i] += t;
        __syncthreads();
    }
    if (i < NSB) g_bsum[i] = s[i] - v;
    if (i == 255) g_offs[N_NODESC] = s[255];
}

__global__ void k_scan3() {   // offsets + cursor + dinv
    int i = blockIdx.x * blockDim.x + threadIdx.x;
    if (i < N_NODESC) {
        int o = g_offs[i] + g_bsum[i >> 9];
        g_offs[i] = o;
        g_cursor[i] = o;
        g_dinv[i] = rsqrtf((float)(g_indeg[i] + 1));   // +1 self loop
    }
}

__global__ void k_scatter(const int* __restrict__ ei) {
    int e = blockIdx.x * blockDim.x + threadIdx.x;
    if (e < N_EDGESC) {
        int is64 = g_is64;
        int src = load_src(ei, e, is64);
        int dst = load_dst(ei, e, is64);
        if ((unsigned)src >= N_NODESC || (unsigned)dst >= N_NODESC) return;
        int p = atomicAdd(&g_cursor[dst], 1);
        if ((unsigned)p < N_EDGESC) g_src[p] = src;
    }
}

// ===== MLP layer 1 : mma.sync bf16 hi/lo + ldmatrix + register pipeline =====
#define BM  128
#define BKc 32
#define APAD 40    // bf16 elems per smem row -> 80B stride (16B-aligned, conflict-free)

__device__ __forceinline__ void mma_bf16(float& c0, float& c1, float& c2, float& c3,
                                         uint32_t a0, uint32_t a1, uint32_t a2, uint32_t a3,
                                         uint32_t b0, uint32_t b1) {
    asm volatile(
        "mma.sync.aligned.m16n8k16.row.col.f32.bf16.bf16.f32 "
        "{%0,%1,%2,%3}, {%4,%5,%6,%7}, {%8,%9}, {%0,%1,%2,%3};"
        : "+f"(c0), "+f"(c1), "+f"(c2), "+f"(c3)
        : "r"(a0), "r"(a1), "r"(a2), "r"(a3), "r"(b0), "r"(b1));
}

__device__ __forceinline__ void ldmat_x4(uint32_t& r0, uint32_t& r1,
                                         uint32_t& r2, uint32_t& r3, uint32_t addr) {
    asm volatile("ldmatrix.sync.aligned.m8n8.x4.shared.b16 {%0,%1,%2,%3}, [%4];"
                 : "=r"(r0), "=r"(r1), "=r"(r2), "=r"(r3) : "r"(addr));
}

__device__ __forceinline__ uint16_t bfbits(__nv_bfloat16 h) {
    return *reinterpret_cast<uint16_t*>(&h);
}

// convert 8 floats -> uint4 of bf16 hi, and uint4 of bf16 lo
__device__ __forceinline__ void cvt8_hilo(const float* v, uint4& hi, uint4& lo) {
    uint32_t hp[4], lp[4];
    #pragma unroll
    for (int p = 0; p < 4; p++) {
        __nv_bfloat16 h0 = __float2bfloat16(v[2 * p]);
        __nv_bfloat16 h1 = __float2bfloat16(v[2 * p + 1]);
        hp[p] = (uint32_t)bfbits(h0) | ((uint32_t)bfbits(h1) << 16);
        float l0 = v[2 * p]     - __bfloat162float(h0);
        float l1 = v[2 * p + 1] - __bfloat162float(h1);
        lp[p] = (uint32_t)bfbits(__float2bfloat16(l0)) |
                ((uint32_t)bfbits(__float2bfloat16(l1)) << 16);
    }
    hi = make_uint4(hp[0], hp[1], hp[2], hp[3]);
    lo = make_uint4(lp[0], lp[1], lp[2], lp[3]);
}

__global__ __launch_bounds__(256, 2) void k_mlp1(const float* __restrict__ x,
                                                 const float* __restrict__ w1,
                                                 const float* __restrict__ b1) {
    __shared__ __nv_bfloat16 Ah[BM][APAD], Al[BM][APAD];
    __shared__ __nv_bfloat16 Bh[HID][APAD], Bl[HID][APAD];
    int tid = threadIdx.x;
    int wid = tid >> 5, lane = tid & 31;
    int grp = lane >> 2, four = lane & 3;
    int blockRow = blockIdx.x * BM;
    int m0 = wid * 16;

    // A staging mapping (constant across chunks): 2 segments of 8 elems
    int a0row = (tid) >> 2,        a0sc = (tid) & 3;
    int a1row = (tid + 256) >> 2,  a1sc = (tid + 256) & 3;
    int ga0 = blockRow + a0row, ga1 = blockRow + a1row;
    // B staging mapping
    int bkseg = tid >> 6;        // 0..3 (k-segment of 8)
    int bn    = tid & 63;        // n

    // ldmatrix addressing
    int a_row = m0 + (lane & 15);
    int a_kof = (lane >> 4) << 3;
    int b_rof = (lane & 7) + ((lane >> 4) << 3);
    int b_kof = ((lane >> 3) & 1) << 3;

    float c[8][4];
    #pragma unroll
    for (int j = 0; j < 8; j++)
        #pragma unroll
        for (int q = 0; q < 4; q++) c[j][q] = 0.f;

    float va[16], vb[8];

    #define LOAD_CHUNK(KK) do {                                                 \
        if (ga0 < N_NODESC) {                                                   \
            const float* xp = &x[(size_t)ga0 * NFEAT + (KK) + a0sc * 8];        \
            float4 v0 = *(const float4*)xp, v1 = *(const float4*)(xp + 4);      \
            va[0] = v0.x; va[1] = v0.y; va[2] = v0.z; va[3] = v0.w;             \
            va[4] = v1.x; va[5] = v1.y; va[6] = v1.z; va[7] = v1.w;             \
        } else { _Pragma("unroll") for (int e = 0; e < 8; e++) va[e] = 0.f; }   \
        if (ga1 < N_NODESC) {                                                   \
            const float* xp = &x[(size_t)ga1 * NFEAT + (KK) + a1sc * 8];        \
            float4 v0 = *(const float4*)xp, v1 = *(const float4*)(xp + 4);      \
            va[8]  = v0.x; va[9]  = v0.y; va[10] = v0.z; va[11] = v0.w;         \
            va[12] = v1.x; va[13] = v1.y; va[14] = v1.z; va[15] = v1.w;         \
        } else { _Pragma("unroll") for (int e = 0; e < 8; e++) va[8 + e] = 0.f; } \
        _Pragma("unroll")                                                       \
        for (int i = 0; i < 8; i++)                                             \
            vb[i] = w1[(size_t)((KK) + bkseg * 8 + i) * HID + bn];              \
    } while (0)

    LOAD_CHUNK(0);

    for (int kk = 0; kk < NFEAT; kk += BKc) {
        // ---- stage registers (chunk kk) -> smem ----
        {
            uint4 hi, lo;
            cvt8_hilo(va, hi, lo);
            *(uint4*)&Ah[a0row][a0sc * 8] = hi;
            *(uint4*)&Al[a0row][a0sc * 8] = lo;
            cvt8_hilo(va + 8, hi, lo);
            *(uint4*)&Ah[a1row][a1sc * 8] = hi;
            *(uint4*)&Al[a1row][a1sc * 8] = lo;
            cvt8_hilo(vb, hi, lo);
            *(uint4*)&Bh[bn][bkseg * 8] = hi;
            *(uint4*)&Bl[bn][bkseg * 8] = lo;
        }
        __syncthreads();

        // ---- prefetch next chunk into registers (hidden under MMA) ----
        if (kk + BKc < NFEAT) LOAD_CHUNK(kk + BKc);

        #pragma unroll
        for (int ks = 0; ks < 2; ks++) {
            int k0 = ks * 16;
            uint32_t ah[4], al[4];
            ldmat_x4(ah[0], ah[1], ah[2], ah[3],
                     (uint32_t)__cvta_generic_to_shared(&Ah[a_row][k0 + a_kof]));
            ldmat_x4(al[0], al[1], al[2], al[3],
                     (uint32_t)__cvta_generic_to_shared(&Al[a_row][k0 + a_kof]));
            #pragma unroll
            for (int q = 0; q < 4; q++) {
                uint32_t bh[4], bl[4];
                int brow = 16 * q + b_rof;
                ldmat_x4(bh[0], bh[1], bh[2], bh[3],
                         (uint32_t)__cvta_generic_to_shared(&Bh[brow][k0 + b_kof]));
                ldmat_x4(bl[0], bl[1], bl[2], bl[3],
                         (uint32_t)__cvta_generic_to_shared(&Bl[brow][k0 + b_kof]));
                int j0 = 2 * q, j1 = 2 * q + 1;
                mma_bf16(c[j0][0], c[j0][1], c[j0][2], c[j0][3],
                         ah[0], ah[1], ah[2], ah[3], bh[0], bh[1]);
                mma_bf16(c[j0][0], c[j0][1], c[j0][2], c[j0][3],
                         al[0], al[1], al[2], al[3], bh[0], bh[1]);
                mma_bf16(c[j0][0], c[j0][1], c[j0][2], c[j0][3],
                         ah[0], ah[1], ah[2], ah[3], bl[0], bl[1]);
                mma_bf16(c[j1][0], c[j1][1], c[j1][2], c[j1][3],
                         ah[0], ah[1], ah[2], ah[3], bh[2], bh[3]);
                mma_bf16(c[j1][0], c[j1][1], c[j1][2], c[j1][3],
                         al[0], al[1], al[2], al[3], bh[2], bh[3]);
                mma_bf16(c[j1][0], c[j1][1], c[j1][2], c[j1][3],
                         ah[0], ah[1], ah[2], ah[3], bl[2], bl[3]);
            }
        }
        __syncthreads();
    }
    #undef LOAD_CHUNK

    // epilogue: c[j] holds rows (m0+grp, m0+grp+8), cols (8j+2*four, +1)
    #pragma unroll
    for (int j = 0; j < 8; j++) {
        int col = j * 8 + four * 2;
        float bb0 = b1[col], bb1 = b1[col + 1];
        int r0 = blockRow + m0 + grp;
        int r1 = r0 + 8;
        if (r0 < N_NODESC) {
            float2 o;
            o.x = fmaxf(c[j][0] + bb0, 0.f);
            o.y = fmaxf(c[j][1] + bb1, 0.f);
            *(float2*)&g_h1[(size_t)r0 * HID + col] = o;
        }
        if (r1 < N_NODESC) {
            float2 o;
            o.x = fmaxf(c[j][2] + bb0, 0.f);
            o.y = fmaxf(c[j][3] + bb1, 0.f);
            *(float2*)&g_h1[(size_t)r1 * HID + col] = o;
        }
    }
}

// ------- MLP layer 2 : h2 = h1 @ w2 + b2 ; write s_0 = dinv * h2 (fp16) -------
__global__ __launch_bounds__(128) void k_mlp2(const float* __restrict__ w2,
                                              const float* __restrict__ b2) {
    __shared__ float ws[HID * NCLS];
    __shared__ float bs[NCLS];
    __shared__ float hs[128 * (HID + 1)];
    int tid = threadIdx.x;
    for (int i = tid; i < HID * NCLS; i += 128) ws[i] = w2[i];
    if (tid < NCLS) bs[tid] = b2[tid];
    int base = blockIdx.x * 128;
    #pragma unroll
    for (int i = 0; i < HID; i++) {
        int f = tid + 128 * i;
        int row = f >> 6, c = f & 63;
        int g = base + row;
        hs[row * (HID + 1) + c] = (g < N_NODESC) ? g_h1[(size_t)g * HID + c] : 0.f;
    }
    __syncthreads();
    int node = base + tid;
    if (node >= N_NODESC) return;
    float acc[NCLS];
    #pragma unroll
    for (int c = 0; c < NCLS; c++) acc[c] = bs[c];
    #pragma unroll 4
    for (int j = 0; j < HID; j++) {
        float hj = hs[tid * (HID + 1) + j];
        #pragma unroll
        for (int c = 0; c < NCLS; c++) acc[c] = fmaf(hj, ws[j * NCLS + c], acc[c]);
    }
    float di = g_dinv[node];
    __half2* s0 = (__half2*)((char*)g_hist + (size_t)node * SROWB);
    #pragma unroll
    for (int i = 0; i < H2ROW; i++)
        s0[i] = __floats2half2_rn(di * acc[2 * i], di * acc[2 * i + 1]);
}

// ------- propagation (s-form): s_{k+1}[d] = dinv[d]^2 * (sum_e s_k[src] + s_k[d])
__global__ __launch_bounds__(320) void k_gather(int kstep) {
    const char* __restrict__ cur = (const char*)g_hist + (size_t)kstep * N_NODESC * SROWB;
    char* __restrict__ nxt = (char*)g_hist + (size_t)(kstep + 1) * N_NODESC * SROWB;
    int t = blockIdx.x * 320 + threadIdx.x;
    int node = t / 5;
    int lane = t - node * 5;
    if (node >= N_NODESC) return;
    int beg = g_offs[node];
    int end = g_offs[node + 1];
    int lb = lane * 16;
    float a0 = 0.f, a1 = 0.f, a2 = 0.f, a3 = 0.f,
          a4 = 0.f, a5 = 0.f, a6 = 0.f, a7 = 0.f;
    #pragma unroll 8
    for (int e = beg; e < end; ++e) {
        int src = __ldg(&g_src[e]);
        uint4 p = __ldg((const uint4*)(cur + (size_t)src * SROWB + lb));
        float2 v;
        v = __half22float2(*(__half2*)&p.x); a0 += v.x; a1 += v.y;
        v = __half22float2(*(__half2*)&p.y); a2 += v.x; a3 += v.y;
        v = __half22float2(*(__half2*)&p.z); a4 += v.x; a5 += v.y;
        v = __half22float2(*(__half2*)&p.w); a6 += v.x; a7 += v.y;
    }
    float di = g_dinv[node];
    float di2 = di * di;
    uint4 mr = *(const uint4*)(cur + (size_t)node * SROWB + lb);
    float2 m;
    float r[8];
    m = __half22float2(*(__half2*)&mr.x); r[0] = di2 * (a0 + m.x); r[1] = di2 * (a1 + m.y);
    m = __half22float2(*(__half2*)&mr.y); r[2] = di2 * (a2 + m.x); r[3] = di2 * (a3 + m.y);
    m = __half22float2(*(__half2*)&mr.z); r[4] = di2 * (a4 + m.x); r[5] = di2 * (a5 + m.y);
    m = __half22float2(*(__half2*)&mr.w); r[6] = di2 * (a6 + m.x); r[7] = di2 * (a7 + m.y);
    uint4 nw;
    __half2 h;
    h = __floats2half2_rn(r[0], r[1]); nw.x = *(uint32_t*)&h;
    h = __floats2half2_rn(r[2], r[3]); nw.y = *(uint32_t*)&h;
    h = __floats2half2_rn(r[4], r[5]); nw.z = *(uint32_t*)&h;
    h = __floats2half2_rn(r[6], r[7]); nw.w = *(uint32_t*)&h;
    *(uint4*)(nxt + (size_t)node * SROWB + lb) = nw;
}

// ------- final: out = log_softmax( sqrtdeg * sum_k gamma_k * s_k ) -------
__global__ __launch_bounds__(256) void k_final(const float* __restrict__ temp,
                                               float* __restrict__ out) {
    int node = blockIdx.x * blockDim.x + threadIdx.x;
    if (node >= N_NODESC) return;
    float acc[NCLS];
    #pragma unroll
    for (int c = 0; c < NCLS; c++) acc[c] = 0.f;
    const char* base = (const char*)g_hist + (size_t)node * SROWB;
    #pragma unroll
    for (int k = 0; k <= KPROP; k++) {
        float gamma = fmaxf(__ldg(&temp[k]), 0.f);
        const char* row = base + (size_t)k * N_NODESC * SROWB;
        #pragma unroll
        for (int q = 0; q < 5; q++) {
            uint4 p = __ldg((const uint4*)(row + q * 16));
            float2 v;
            v = __half22float2(*(__half2*)&p.x);
            acc[q * 8 + 0] = fmaf(gamma, v.x, acc[q * 8 + 0]);
            acc[q * 8 + 1] = fmaf(gamma, v.y, acc[q * 8 + 1]);
            v = __half22float2(*(__half2*)&p.y);
            acc[q * 8 + 2] = fmaf(gamma, v.x, acc[q * 8 + 2]);
            acc[q * 8 + 3] = fmaf(gamma, v.y, acc[q * 8 + 3]);
            v = __half22float2(*(__half2*)&p.z);
            acc[q * 8 + 4] = fmaf(gamma, v.x, acc[q * 8 + 4]);
            acc[q * 8 + 5] = fmaf(gamma, v.y, acc[q * 8 + 5]);
            v = __half22float2(*(__half2*)&p.w);
            acc[q * 8 + 6] = fmaf(gamma, v.x, acc[q * 8 + 6]);
            acc[q * 8 + 7] = fmaf(gamma, v.y, acc[q * 8 + 7]);
        }
    }
    float sd = 1.0f / g_dinv[node];      // sqrt(deg)
    float mx = -1e30f;
    #pragma unroll
    for (int c = 0; c < NCLS; c++) { acc[c] *= sd; mx = fmaxf(mx, acc[c]); }
    float s = 0.f;
    #pragma unroll
    for (int c = 0; c < NCLS; c++) s += expf(acc[c] - mx);
    float l = mx + logf(s);
    float4* q = (float4*)(out + (size_t)node * NCLS);
    #pragma unroll
    for (int i = 0; i < NCLS / 4; i++) {
        float4 w;
        w.x = acc[4 * i]     - l; w.y = acc[4 * i + 1] - l;
        w.z = acc[4 * i + 2] - l; w.w = acc[4 * i + 3] - l;
        q[i] = w;
    }
}

// ---- persistent stream/event handles (created once on the uncaptured
// correctness call; same launch DAG every call -> deterministic) ----
static cudaStream_t g_s2 = nullptr;
static cudaEvent_t  g_ev0 = nullptr, g_ev1 = nullptr;

extern "C" void kernel_launch(void* const* d_in, const int* in_sizes, int n_in,
                              void* d_out, int out_size) {
    const float* x    = (const float*)d_in[0];
    const int*   ei   = (const int*)d_in[1];     // int32 or int64 (auto-detected)
    const float* w1   = (const float*)d_in[2];
    const float* b1   = (const float*)d_in[3];
    const float* w2   = (const float*)d_in[4];
    const float* b2   = (const float*)d_in[5];
    const float* temp = (const float*)d_in[6];
    float* out = (float*)d_out;

    if (!g_s2) {
        cudaStreamCreateWithFlags(&g_s2, cudaStreamNonBlocking);
        cudaEventCreateWithFlags(&g_ev0, cudaEventDisableTiming);
        cudaEventCreateWithFlags(&g_ev1, cudaEventDisableTiming);
    }

    int nb_nodes = (N_NODESC + 255) / 256;
    int nb_edges = (N_EDGESC + 255) / 256;

    // fork: preprocessing on g_s2 (atomic/L2-bound), MLP1 on stream 0 (smem/tensor)
    cudaEventRecord(g_ev0, 0);
    cudaStreamWaitEvent(g_s2, g_ev0, 0);

    k_detect<<<1, 32, 0, g_s2>>>(ei);                          // 1
    k_zero<<<nb_nodes, 256, 0, g_s2>>>();                      // 2
    k_count<<<nb_edges, 256, 0, g_s2>>>(ei);                   // 3
    k_mlp1<<<(N_NODESC + BM - 1) / BM, 256>>>(x, w1, b1);      // 4 (profiled slot)
    k_scan1<<<NSB, SCAN_B, 0, g_s2>>>();
    k_scan2p<<<1, 256, 0, g_s2>>>();
    k_scan3<<<nb_nodes, 256, 0, g_s2>>>();
    k_scatter<<<nb_edges, 256, 0, g_s2>>>(ei);
    cudaEventRecord(g_ev1, g_s2);

    // join: mlp2 needs h1 (stream 0) and dinv (g_s2)
    cudaStreamWaitEvent(0, g_ev1, 0);
    k_mlp2<<<(N_NODESC + 127) / 128, 128>>>(w2, b2);
    for (int k = 0; k < KPROP; k++)
        k_gather<<<(N_NODESC * 5 + 319) / 320, 320>>>(k);
    k_final<<<nb_nodes, 256>>>(temp, out);
}

// round 13
// speedup vs baseline: 1.5490x; 1.5490x over previous
#include <cuda_runtime.h>
#include <cuda_fp16.h>
#include <cuda_bf16.h>
#include <cstdint>

#define N_NODESC 100000
#define NFEAT    512
#define HID      64
#define NCLS     40
#define N_EDGESC 3200000
#define KPROP    10
#define H2ROW    (NCLS / 2)          // 20 half2 = 80B per node row
#define ROWB     80

#define SCAN_B 512
#define NSB ((N_NODESC + SCAN_B - 1) / SCAN_B)   // 196

typedef unsigned long long ull;

// ---- static scratch (no allocations allowed) ----
__device__ int     g_is64;
__device__ int     g_indeg[N_NODESC];
__device__ float   g_dinv[N_NODESC];
__device__ int     g_offs[N_NODESC + 1];
__device__ int     g_cursor[N_NODESC];
__device__ int     g_bsum[NSB];
__device__ int     g_src[N_EDGESC];
__device__ float   g_h1[(size_t)N_NODESC * HID];
__device__ __half2 g_hist[(size_t)(KPROP + 1) * N_NODESC * H2ROW];   // s_0..s_10

// ---------------- dtype detection: int64 edge_index has zero high words ----
__global__ void k_detect(const int* __restrict__ ei) {
    int nz = 0;
    for (int t = threadIdx.x; t < 64; t += 32)
        nz |= (ei[2 * t + 1] != 0);
    unsigned b = __ballot_sync(0xffffffffu, nz);
    if (threadIdx.x == 0) g_is64 = (b == 0u);
}

__device__ __forceinline__ int load_src(const int* ei, int e, int is64) {
    return is64 ? ei[2 * e] : ei[e];
}
__device__ __forceinline__ int load_dst(const int* ei, int e, int is64) {
    return is64 ? ei[2 * (N_EDGESC + e)] : ei[N_EDGESC + e];
}

// ---------------- preprocessing ----------------
__global__ void k_zero() {
    int i = blockIdx.x * blockDim.x + threadIdx.x;
    if (i < N_NODESC) g_indeg[i] = 0;
}

__global__ void k_count(const int* __restrict__ ei) {
    int e = blockIdx.x * blockDim.x + threadIdx.x;
    if (e < N_EDGESC) {
        int dst = load_dst(ei, e, g_is64);
        if ((unsigned)dst < N_NODESC) atomicAdd(&g_indeg[dst], 1);
    }
}

__global__ void k_scan1() {
    __shared__ int s[SCAN_B];
    int i = blockIdx.x * SCAN_B + threadIdx.x;
    int v = (i < N_NODESC) ? g_indeg[i] : 0;
    s[threadIdx.x] = v;
    __syncthreads();
    #pragma unroll
    for (int off = 1; off < SCAN_B; off <<= 1) {
        int t = (threadIdx.x >= off) ? s[threadIdx.x - off] : 0;
        __syncthreads();
        s[threadIdx.x] += t;
        __syncthreads();
    }
    if (i < N_NODESC) g_offs[i] = s[threadIdx.x] - v;
    if (threadIdx.x == SCAN_B - 1) g_bsum[blockIdx.x] = s[SCAN_B - 1];
}

__global__ void k_scan2p() {
    __shared__ int s[256];
    int i = threadIdx.x;
    int v = (i < NSB) ? g_bsum[i] : 0;
    s[i] = v;
    __syncthreads();
    #pragma unroll
    for (int off = 1; off < 256; off <<= 1) {
        int t = (i >= off) ? s[i - off] : 0;
        __syncthreads();
        s[i] += t;
        __syncthreads();
    }
    if (i < NSB) g_bsum[i] = s[i] - v;
    if (i == 255) g_offs[N_NODESC] = s[255];
}

__global__ void k_scan3() {   // offsets + cursor + dinv
    int i = blockIdx.x * blockDim.x + threadIdx.x;
    if (i < N_NODESC) {
        int o = g_offs[i] + g_bsum[i >> 9];
        g_offs[i] = o;
        g_cursor[i] = o;
        g_dinv[i] = rsqrtf((float)(g_indeg[i] + 1));   // +1 self loop
    }
}

__global__ void k_scatter(const int* __restrict__ ei) {
    int e = blockIdx.x * blockDim.x + threadIdx.x;
    if (e < N_EDGESC) {
        int is64 = g_is64;
        int src = load_src(ei, e, is64);
        int dst = load_dst(ei, e, is64);
        if ((unsigned)src >= N_NODESC || (unsigned)dst >= N_NODESC) return;
        int p = atomicAdd(&g_cursor[dst], 1);
        if ((unsigned)p < N_EDGESC) g_src[p] = src;
    }
}

// ===== MLP layer 1 : mma.sync bf16 hi/lo + ldmatrix + register pipeline =====
#define BM  128
#define BKc 32
#define APAD 40    // bf16 elems per smem row -> 80B stride (16B-aligned, conflict-free)

__device__ __forceinline__ void mma_bf16(float& c0, float& c1, float& c2, float& c3,
                                         uint32_t a0, uint32_t a1, uint32_t a2, uint32_t a3,
                                         uint32_t b0, uint32_t b1) {
    asm volatile(
        "mma.sync.aligned.m16n8k16.row.col.f32.bf16.bf16.f32 "
        "{%0,%1,%2,%3}, {%4,%5,%6,%7}, {%8,%9}, {%0,%1,%2,%3};"
        : "+f"(c0), "+f"(c1), "+f"(c2), "+f"(c3)
        : "r"(a0), "r"(a1), "r"(a2), "r"(a3), "r"(b0), "r"(b1));
}

__device__ __forceinline__ void ldmat_x4(uint32_t& r0, uint32_t& r1,
                                         uint32_t& r2, uint32_t& r3, uint32_t addr) {
    asm volatile("ldmatrix.sync.aligned.m8n8.x4.shared.b16 {%0,%1,%2,%3}, [%4];"
                 : "=r"(r0), "=r"(r1), "=r"(r2), "=r"(r3) : "r"(addr));
}

__device__ __forceinline__ uint16_t bfbits(__nv_bfloat16 h) {
    return *reinterpret_cast<uint16_t*>(&h);
}

// convert 8 floats -> uint4 of bf16 hi, and uint4 of bf16 lo
__device__ __forceinline__ void cvt8_hilo(const float* v, uint4& hi, uint4& lo) {
    uint32_t hp[4], lp[4];
    #pragma unroll
    for (int p = 0; p < 4; p++) {
        __nv_bfloat16 h0 = __float2bfloat16(v[2 * p]);
        __nv_bfloat16 h1 = __float2bfloat16(v[2 * p + 1]);
        hp[p] = (uint32_t)bfbits(h0) | ((uint32_t)bfbits(h1) << 16);
        float l0 = v[2 * p]     - __bfloat162float(h0);
        float l1 = v[2 * p + 1] - __bfloat162float(h1);
        lp[p] = (uint32_t)bfbits(__float2bfloat16(l0)) |
                ((uint32_t)bfbits(__float2bfloat16(l1)) << 16);
    }
    hi = make_uint4(hp[0], hp[1], hp[2], hp[3]);
    lo = make_uint4(lp[0], lp[1], lp[2], lp[3]);
}

__global__ __launch_bounds__(256, 2) void k_mlp1(const float* __restrict__ x,
                                                 const float* __restrict__ w1,
                                                 const float* __restrict__ b1) {
    __shared__ __nv_bfloat16 Ah[BM][APAD], Al[BM][APAD];
    __shared__ __nv_bfloat16 Bh[HID][APAD], Bl[HID][APAD];
    int tid = threadIdx.x;
    int wid = tid >> 5, lane = tid & 31;
    int grp = lane >> 2, four = lane & 3;
    int blockRow = blockIdx.x * BM;
    int m0 = wid * 16;

    // A staging mapping (constant across chunks): 2 segments of 8 elems
    int a0row = (tid) >> 2,        a0sc = (tid) & 3;
    int a1row = (tid + 256) >> 2,  a1sc = (tid + 256) & 3;
    int ga0 = blockRow + a0row, ga1 = blockRow + a1row;
    // B staging mapping
    int bkseg = tid >> 6;        // 0..3 (k-segment of 8)
    int bn    = tid & 63;        // n

    // ldmatrix addressing
    int a_row = m0 + (lane & 15);
    int a_kof = (lane >> 4) << 3;
    int b_rof = (lane & 7) + ((lane >> 4) << 3);
    int b_kof = ((lane >> 3) & 1) << 3;

    float c[8][4];
    #pragma unroll
    for (int j = 0; j < 8; j++)
        #pragma unroll
        for (int q = 0; q < 4; q++) c[j][q] = 0.f;

    float va[16], vb[8];

    #define LOAD_CHUNK(KK) do {                                                 \
        if (ga0 < N_NODESC) {                                                   \
            const float* xp = &x[(size_t)ga0 * NFEAT + (KK) + a0sc * 8];        \
            float4 v0 = *(const float4*)xp, v1 = *(const float4*)(xp + 4);      \
            va[0] = v0.x; va[1] = v0.y; va[2] = v0.z; va[3] = v0.w;             \
            va[4] = v1.x; va[5] = v1.y; va[6] = v1.z; va[7] = v1.w;             \
        } else { _Pragma("unroll") for (int e = 0; e < 8; e++) va[e] = 0.f; }   \
        if (ga1 < N_NODESC) {                                                   \
            const float* xp = &x[(size_t)ga1 * NFEAT + (KK) + a1sc * 8];        \
            float4 v0 = *(const float4*)xp, v1 = *(const float4*)(xp + 4);      \
            va[8]  = v0.x; va[9]  = v0.y; va[10] = v0.z; va[11] = v0.w;         \
            va[12] = v1.x; va[13] = v1.y; va[14] = v1.z; va[15] = v1.w;         \
        } else { _Pragma("unroll") for (int e = 0; e < 8; e++) va[8 + e] = 0.f; } \
        _Pragma("unroll")                                                       \
        for (int i = 0; i < 8; i++)                                             \
            vb[i] = w1[(size_t)((KK) + bkseg * 8 + i) * HID + bn];              \
    } while (0)

    LOAD_CHUNK(0);

    for (int kk = 0; kk < NFEAT; kk += BKc) {
        // ---- stage registers (chunk kk) -> smem ----
        {
            uint4 hi, lo;
            cvt8_hilo(va, hi, lo);
            *(uint4*)&Ah[a0row][a0sc * 8] = hi;
            *(uint4*)&Al[a0row][a0sc * 8] = lo;
            cvt8_hilo(va + 8, hi, lo);
            *(uint4*)&Ah[a1row][a1sc * 8] = hi;
            *(uint4*)&Al[a1row][a1sc * 8] = lo;
            cvt8_hilo(vb, hi, lo);
            *(uint4*)&Bh[bn][bkseg * 8] = hi;
            *(uint4*)&Bl[bn][bkseg * 8] = lo;
        }
        __syncthreads();

        // ---- prefetch next chunk into registers (hidden under MMA) ----
        if (kk + BKc < NFEAT) LOAD_CHUNK(kk + BKc);

        #pragma unroll
        for (int ks = 0; ks < 2; ks++) {
            int k0 = ks * 16;
            uint32_t ah[4], al[4];
            ldmat_x4(ah[0], ah[1], ah[2], ah[3],
                     (uint32_t)__cvta_generic_to_shared(&Ah[a_row][k0 + a_kof]));
            ldmat_x4(al[0], al[1], al[2], al[3],
                     (uint32_t)__cvta_generic_to_shared(&Al[a_row][k0 + a_kof]));
            #pragma unroll
            for (int q = 0; q < 4; q++) {
                uint32_t bh[4], bl[4];
                int brow = 16 * q + b_rof;
                ldmat_x4(bh[0], bh[1], bh[2], bh[3],
                         (uint32_t)__cvta_generic_to_shared(&Bh[brow][k0 + b_kof]));
                ldmat_x4(bl[0], bl[1], bl[2], bl[3],
                         (uint32_t)__cvta_generic_to_shared(&Bl[brow][k0 + b_kof]));
                int j0 = 2 * q, j1 = 2 * q + 1;
                mma_bf16(c[j0][0], c[j0][1], c[j0][2], c[j0][3],
                         ah[0], ah[1], ah[2], ah[3], bh[0], bh[1]);
                mma_bf16(c[j0][0], c[j0][1], c[j0][2], c[j0][3],
                         al[0], al[1], al[2], al[3], bh[0], bh[1]);
                mma_bf16(c[j0][0], c[j0][1], c[j0][2], c[j0][3],
                         ah[0], ah[1], ah[2], ah[3], bl[0], bl[1]);
                mma_bf16(c[j1][0], c[j1][1], c[j1][2], c[j1][3],
                         ah[0], ah[1], ah[2], ah[3], bh[2], bh[3]);
                mma_bf16(c[j1][0], c[j1][1], c[j1][2], c[j1][3],
                         al[0], al[1], al[2], al[3], bh[2], bh[3]);
                mma_bf16(c[j1][0], c[j1][1], c[j1][2], c[j1][3],
                         ah[0], ah[1], ah[2], ah[3], bl[2], bl[3]);
            }
        }
        __syncthreads();
    }
    #undef LOAD_CHUNK

    // epilogue: c[j] holds rows (m0+grp, m0+grp+8), cols (8j+2*four, +1)
    #pragma unroll
    for (int j = 0; j < 8; j++) {
        int col = j * 8 + four * 2;
        float bb0 = b1[col], bb1 = b1[col + 1];
        int r0 = blockRow + m0 + grp;
        int r1 = r0 + 8;
        if (r0 < N_NODESC) {
            float2 o;
            o.x = fmaxf(c[j][0] + bb0, 0.f);
            o.y = fmaxf(c[j][1] + bb1, 0.f);
            *(float2*)&g_h1[(size_t)r0 * HID + col] = o;
        }
        if (r1 < N_NODESC) {
            float2 o;
            o.x = fmaxf(c[j][2] + bb0, 0.f);
            o.y = fmaxf(c[j][3] + bb1, 0.f);
            *(float2*)&g_h1[(size_t)r1 * HID + col] = o;
        }
    }
}

// ------- MLP layer 2 : h2 = h1 @ w2 + b2 ; write s_0 = dinv * h2 (fp16) -------
__global__ __launch_bounds__(128) void k_mlp2(const float* __restrict__ w2,
                                              const float* __restrict__ b2) {
    __shared__ float ws[HID * NCLS];
    __shared__ float bs[NCLS];
    __shared__ float hs[128 * (HID + 1)];
    int tid = threadIdx.x;
    for (int i = tid; i < HID * NCLS; i += 128) ws[i] = w2[i];
    if (tid < NCLS) bs[tid] = b2[tid];
    int base = blockIdx.x * 128;
    #pragma unroll
    for (int i = 0; i < HID; i++) {
        int f = tid + 128 * i;
        int row = f >> 6, c = f & 63;
        int g = base + row;
        hs[row * (HID + 1) + c] = (g < N_NODESC) ? g_h1[(size_t)g * HID + c] : 0.f;
    }
    __syncthreads();
    int node = base + tid;
    if (node >= N_NODESC) return;
    float acc[NCLS];
    #pragma unroll
    for (int c = 0; c < NCLS; c++) acc[c] = bs[c];
    #pragma unroll 4
    for (int j = 0; j < HID; j++) {
        float hj = hs[tid * (HID + 1) + j];
        #pragma unroll
        for (int c = 0; c < NCLS; c++) acc[c] = fmaf(hj, ws[j * NCLS + c], acc[c]);
    }
    float di = g_dinv[node];
    __half2* s0 = g_hist + (size_t)node * H2ROW;
    #pragma unroll
    for (int i = 0; i < H2ROW; i++)
        s0[i] = __floats2half2_rn(di * acc[2 * i], di * acc[2 * i + 1]);
}

// ------- propagation (s-form): s_{k+1}[d] = dinv[d]^2 * (sum_e s_k[src] + s_k[d])
__global__ __launch_bounds__(320) void k_gather(int kstep) {
    const char* __restrict__ cur = (const char*)(g_hist + (size_t)kstep * N_NODESC * H2ROW);
    char* __restrict__ nxt = (char*)(g_hist + (size_t)(kstep + 1) * N_NODESC * H2ROW);
    int t = blockIdx.x * 320 + threadIdx.x;
    int node = t / 5;
    int lane = t - node * 5;
    if (node >= N_NODESC) return;
    int beg = g_offs[node];
    int end = g_offs[node + 1];
    int lb = lane * 16;
    float a0 = 0.f, a1 = 0.f, a2 = 0.f, a3 = 0.f,
          a4 = 0.f, a5 = 0.f, a6 = 0.f, a7 = 0.f;
    #pragma unroll 4
    for (int e = beg; e < end; ++e) {
        int src = __ldg(&g_src[e]);
        uint4 p = __ldg((const uint4*)(cur + (size_t)src * ROWB + lb));
        float2 v;
        v = __half22float2(*(__half2*)&p.x); a0 += v.x; a1 += v.y;
        v = __half22float2(*(__half2*)&p.y); a2 += v.x; a3 += v.y;
        v = __half22float2(*(__half2*)&p.z); a4 += v.x; a5 += v.y;
        v = __half22float2(*(__half2*)&p.w); a6 += v.x; a7 += v.y;
    }
    float di = g_dinv[node];
    float di2 = di * di;
    uint4 mr = *(const uint4*)(cur + (size_t)node * ROWB + lb);
    float2 m;
    float r[8];
    m = __half22float2(*(__half2*)&mr.x); r[0] = di2 * (a0 + m.x); r[1] = di2 * (a1 + m.y);
    m = __half22float2(*(__half2*)&mr.y); r[2] = di2 * (a2 + m.x); r[3] = di2 * (a3 + m.y);
    m = __half22float2(*(__half2*)&mr.z); r[4] = di2 * (a4 + m.x); r[5] = di2 * (a5 + m.y);
    m = __half22float2(*(__half2*)&mr.w); r[6] = di2 * (a6 + m.x); r[7] = di2 * (a7 + m.y);
    uint4 nw;
    __half2 h;
    h = __floats2half2_rn(r[0], r[1]); nw.x = *(uint32_t*)&h;
    h = __floats2half2_rn(r[2], r[3]); nw.y = *(uint32_t*)&h;
    h = __floats2half2_rn(r[4], r[5]); nw.z = *(uint32_t*)&h;
    h = __floats2half2_rn(r[6], r[7]); nw.w = *(uint32_t*)&h;
    *(uint4*)(nxt + (size_t)node * ROWB + lb) = nw;
}

// ------- final: out = log_softmax( sqrtdeg * sum_k gamma_k * s_k ) -------
__global__ __launch_bounds__(256) void k_final(const float* __restrict__ temp,
                                               float* __restrict__ out) {
    int node = blockIdx.x * blockDim.x + threadIdx.x;
    if (node >= N_NODESC) return;
    float acc[NCLS];
    #pragma unroll
    for (int c = 0; c < NCLS; c++) acc[c] = 0.f;
    const char* base = (const char*)g_hist + (size_t)node * ROWB;
    #pragma unroll
    for (int k = 0; k <= KPROP; k++) {
        float gamma = fmaxf(__ldg(&temp[k]), 0.f);
        const char* row = base + (size_t)k * N_NODESC * ROWB;
        #pragma unroll
        for (int q = 0; q < 5; q++) {
            uint4 p = __ldg((const uint4*)(row + q * 16));
            float2 v;
            v = __half22float2(*(__half2*)&p.x);
            acc[q * 8 + 0] = fmaf(gamma, v.x, acc[q * 8 + 0]);
            acc[q * 8 + 1] = fmaf(gamma, v.y, acc[q * 8 + 1]);
            v = __half22float2(*(__half2*)&p.y);
            acc[q * 8 + 2] = fmaf(gamma, v.x, acc[q * 8 + 2]);
            acc[q * 8 + 3] = fmaf(gamma, v.y, acc[q * 8 + 3]);
            v = __half22float2(*(__half2*)&p.z);
            acc[q * 8 + 4] = fmaf(gamma, v.x, acc[q * 8 + 4]);
            acc[q * 8 + 5] = fmaf(gamma, v.y, acc[q * 8 + 5]);
            v = __half22float2(*(__half2*)&p.w);
            acc[q * 8 + 6] = fmaf(gamma, v.x, acc[q * 8 + 6]);
            acc[q * 8 + 7] = fmaf(gamma, v.y, acc[q * 8 + 7]);
        }
    }
    float sd = 1.0f / g_dinv[node];      // sqrt(deg)
    float mx = -1e30f;
    #pragma unroll
    for (int c = 0; c < NCLS; c++) { acc[c] *= sd; mx = fmaxf(mx, acc[c]); }
    float s = 0.f;
    #pragma unroll
    for (int c = 0; c < NCLS; c++) s += expf(acc[c] - mx);
    float l = mx + logf(s);
    float4* q = (float4*)(out + (size_t)node * NCLS);
    #pragma unroll
    for (int i = 0; i < NCLS / 4; i++) {
        float4 w;
        w.x = acc[4 * i]     - l; w.y = acc[4 * i + 1] - l;
        w.z = acc[4 * i + 2] - l; w.w = acc[4 * i + 3] - l;
        q[i] = w;
    }
}

// ---- persistent stream/event handles (created once on the uncaptured
// correctness call; same launch DAG every call -> deterministic) ----
static cudaStream_t g_s2 = nullptr;
static cudaEvent_t  g_ev0 = nullptr, g_ev1 = nullptr;

extern "C" void kernel_launch(void* const* d_in, const int* in_sizes, int n_in,
                              void* d_out, int out_size) {
    const float* x    = (const float*)d_in[0];
    const int*   ei   = (const int*)d_in[1];     // int32 or int64 (auto-detected)
    const float* w1   = (const float*)d_in[2];
    const float* b1   = (const float*)d_in[3];
    const float* w2   = (const float*)d_in[4];
    const float* b2   = (const float*)d_in[5];
    const float* temp = (const float*)d_in[6];
    float* out = (float*)d_out;

    if (!g_s2) {
        cudaStreamCreateWithFlags(&g_s2, cudaStreamNonBlocking);
        cudaEventCreateWithFlags(&g_ev0, cudaEventDisableTiming);
        cudaEventCreateWithFlags(&g_ev1, cudaEventDisableTiming);
    }

    int nb_nodes = (N_NODESC + 255) / 256;
    int nb_edges = (N_EDGESC + 255) / 256;

    // fork: preprocessing on g_s2 (atomic/L2-bound), MLP1 on stream 0 (smem/tensor)
    cudaEventRecord(g_ev0, 0);
    cudaStreamWaitEvent(g_s2, g_ev0, 0);

    k_detect<<<1, 32, 0, g_s2>>>(ei);                          // 1
    k_zero<<<nb_nodes, 256, 0, g_s2>>>();                      // 2
    k_count<<<nb_edges, 256, 0, g_s2>>>(ei);                   // 3
    k_mlp1<<<(N_NODESC + BM - 1) / BM, 256>>>(x, w1, b1);      // 4 (profiled slot)
    k_scan1<<<NSB, SCAN_B, 0, g_s2>>>();
    k_scan2p<<<1, 256, 0, g_s2>>>();
    k_scan3<<<nb_nodes, 256, 0, g_s2>>>();
    k_scatter<<<nb_edges, 256, 0, g_s2>>>(ei);
    cudaEventRecord(g_ev1, g_s2);

    // join: mlp2 needs h1 (stream 0) and dinv (g_s2)
    cudaStreamWaitEvent(0, g_ev1, 0);
    k_mlp2<<<(N_NODESC + 127) / 128, 128>>>(w2, b2);
    for (int k = 0; k < KPROP; k++)
        k_gather<<<(N_NODESC * 5 + 319) / 320, 320>>>(k);
    k_final<<<nb_nodes, 256>>>(temp, out);
}